// round 1
// baseline (speedup 1.0000x reference)
#include <cuda_runtime.h>
#include <math.h>

#define BATCH 8
#define SEQ 1600
#define IN_DIM 256
#define DMODEL 512
#define NHEAD 8
#define HDIM 64
#define NJOINT 25
#define BH (BATCH*NHEAD)                 // 64
#define OUT_ELEMS (BATCH*SEQ*DMODEL)     // 6,553,600
#define PATT_ELEMS ((size_t)BH*SEQ*SEQ)  // 163,840,000
#define NEGC (-9.0e15f)

// scratch (allocation-free rule: __device__ globals)
__device__ float g_q[BH*SEQ*HDIM];
__device__ float g_k[BH*SEQ*HDIM];
__device__ float g_v[BH*SEQ*HDIM];
__device__ float g_rowmax[BH*SEQ];
__device__ float g_rowinv[BH*SEQ];
// fallback score buffer in case harness output does not include p_attn
__device__ float g_scores_fallback[PATT_ELEMS];

// ---------------------------------------------------------------------------
// K1: QKV projection.  out[r, c] = x[r,:] @ W[:, c] + bias[c]  (+ReLU for V)
// 64x64 tile, 256 threads, 4x4 per thread, K chunks of 16.
// Result stored in [b, h, s, d] layout (head-major) in g_q/g_k/g_v.
// ---------------------------------------------------------------------------
__global__ __launch_bounds__(256) void qkv_kernel(
    const float* __restrict__ x,
    const float* __restrict__ wq, const float* __restrict__ bq,
    const float* __restrict__ wk, const float* __restrict__ bk,
    const float* __restrict__ wv, const float* __restrict__ bv)
{
    const float* W; const float* bias; float* dst; bool do_relu;
    int z = blockIdx.z;
    if (z == 0)      { W = wq; bias = bq; dst = g_q; do_relu = false; }
    else if (z == 1) { W = wk; bias = bk; dst = g_k; do_relu = false; }
    else             { W = wv; bias = bv; dst = g_v; do_relu = true;  }

    __shared__ float xsT[16][68];   // [k][m] transposed x tile
    __shared__ float ws[16][64];    // [k][n]

    const int t  = threadIdx.x;
    const int tx = t & 15, ty = t >> 4;
    const int rowBase = blockIdx.y * 64;   // M
    const int nBase   = blockIdx.x * 64;   // N

    const int lr   = t >> 2;          // x-load row 0..63
    const int lseg = (t & 3) * 4;     // x-load k-offset
    const int wkk  = t >> 4;          // w-load k row 0..15
    const int wseg = (t & 15) * 4;    // w-load n-offset

    float acc[4][4] = {};

    for (int k0 = 0; k0 < IN_DIM; k0 += 16) {
        float4 xv = *(const float4*)&x[(size_t)(rowBase + lr) * IN_DIM + k0 + lseg];
        float4 wv4 = *(const float4*)&W[(size_t)(k0 + wkk) * DMODEL + nBase + wseg];
        __syncthreads();
        xsT[lseg + 0][lr] = xv.x;
        xsT[lseg + 1][lr] = xv.y;
        xsT[lseg + 2][lr] = xv.z;
        xsT[lseg + 3][lr] = xv.w;
        *(float4*)&ws[wkk][wseg] = wv4;
        __syncthreads();
        #pragma unroll
        for (int kk = 0; kk < 16; kk++) {
            float4 A = *(float4*)&xsT[kk][ty * 4];
            float4 Bv = *(float4*)&ws[kk][tx * 4];
            float ar[4] = {A.x, A.y, A.z, A.w};
            float br[4] = {Bv.x, Bv.y, Bv.z, Bv.w};
            #pragma unroll
            for (int i = 0; i < 4; i++)
                #pragma unroll
                for (int j = 0; j < 4; j++)
                    acc[i][j] += ar[i] * br[j];
        }
    }

    float4 bb = *(const float4*)&bias[nBase + tx * 4];
    const int h = nBase >> 6;   // 64-wide N tile sits inside one head
    #pragma unroll
    for (int i = 0; i < 4; i++) {
        int r = rowBase + ty * 4 + i;
        int b_ = r / SEQ, s_ = r % SEQ;
        float4 o;
        o.x = acc[i][0] + bb.x;
        o.y = acc[i][1] + bb.y;
        o.z = acc[i][2] + bb.z;
        o.w = acc[i][3] + bb.w;
        if (do_relu) {
            o.x = fmaxf(o.x, 0.f); o.y = fmaxf(o.y, 0.f);
            o.z = fmaxf(o.z, 0.f); o.w = fmaxf(o.w, 0.f);
        }
        *(float4*)&dst[((size_t)(b_ * NHEAD + h) * SEQ + s_) * HDIM + tx * 4] = o;
    }
}

// ---------------------------------------------------------------------------
// K2: raw masked scores.  P[bh, q, k] = (Q[q,:]·K[k,:]) / 8  (NEG if masked)
// 64x64 tile per block, K-dim = 64 fully resident.
// ---------------------------------------------------------------------------
__global__ __launch_bounds__(256) void scores_kernel(float* __restrict__ Pext, int use_ext)
{
    float* P = use_ext ? Pext : g_scores_fallback;
    const int bh = blockIdx.z;
    const int qBase = blockIdx.y * 64;
    const int kBase = blockIdx.x * 64;
    const float* Q = g_q + (size_t)bh * SEQ * HDIM;
    const float* K = g_k + (size_t)bh * SEQ * HDIM;

    __shared__ float qsT[64][68];  // [d][q]
    __shared__ float ksT[64][68];  // [d][k]

    const int t = threadIdx.x;
    const int tx = t & 15, ty = t >> 4;

    #pragma unroll
    for (int p = 0; p < 4; p++) {
        int idx = t + p * 256;
        int r   = idx >> 4;         // 0..63
        int cg  = (idx & 15) * 4;   // 0..60
        float4 qv = *(const float4*)&Q[(size_t)(qBase + r) * HDIM + cg];
        qsT[cg + 0][r] = qv.x; qsT[cg + 1][r] = qv.y;
        qsT[cg + 2][r] = qv.z; qsT[cg + 3][r] = qv.w;
        float4 kv = *(const float4*)&K[(size_t)(kBase + r) * HDIM + cg];
        ksT[cg + 0][r] = kv.x; ksT[cg + 1][r] = kv.y;
        ksT[cg + 2][r] = kv.z; ksT[cg + 3][r] = kv.w;
    }
    __syncthreads();

    float acc[4][4] = {};
    #pragma unroll
    for (int kk = 0; kk < 64; kk++) {
        float4 A = *(float4*)&qsT[kk][ty * 4];
        float4 Bv = *(float4*)&ksT[kk][tx * 4];
        float ar[4] = {A.x, A.y, A.z, A.w};
        float br[4] = {Bv.x, Bv.y, Bv.z, Bv.w};
        #pragma unroll
        for (int i = 0; i < 4; i++)
            #pragma unroll
            for (int j = 0; j < 4; j++)
                acc[i][j] += ar[i] * br[j];
    }

    int kg[4], fk[4];
    #pragma unroll
    for (int j = 0; j < 4; j++) { kg[j] = kBase + tx * 4 + j; fk[j] = kg[j] / NJOINT; }

    #pragma unroll
    for (int i = 0; i < 4; i++) {
        int qg = qBase + ty * 4 + i;
        int fq = qg / NJOINT;
        float4 o;
        float v[4];
        #pragma unroll
        for (int j = 0; j < 4; j++) {
            bool allow = (fq != fk[j]) || (qg == kg[j]);
            v[j] = allow ? acc[i][j] * 0.125f : NEGC;
        }
        o.x = v[0]; o.y = v[1]; o.z = v[2]; o.w = v[3];
        *(float4*)&P[((size_t)bh * SEQ + qg) * SEQ + kBase + tx * 4] = o;
    }
}

// ---------------------------------------------------------------------------
// K3: per-row online softmax stats (max, 1/sumexp). One warp per row.
// ---------------------------------------------------------------------------
__global__ __launch_bounds__(256) void rowstats_kernel(const float* __restrict__ Pext, int use_ext)
{
    const float* P = use_ext ? Pext : g_scores_fallback;
    int row  = blockIdx.x * 8 + (threadIdx.x >> 5);
    int lane = threadIdx.x & 31;
    const float* pr = P + (size_t)row * SEQ;

    float m = -INFINITY, s = 0.f;
    for (int k = lane; k < SEQ; k += 32) {
        float v = pr[k];
        float nm = fmaxf(m, v);
        s = s * __expf(m - nm) + __expf(v - nm);
        m = nm;
    }
    #pragma unroll
    for (int off = 16; off; off >>= 1) {
        float om = __shfl_xor_sync(0xffffffffu, m, off);
        float os = __shfl_xor_sync(0xffffffffu, s, off);
        float nm = fmaxf(m, om);
        s = s * __expf(m - nm) + os * __expf(om - nm);
        m = nm;
    }
    if (lane == 0) { g_rowmax[row] = m; g_rowinv[row] = 1.f / s; }
}

// ---------------------------------------------------------------------------
// K4: fused normalize + write p_attn + out = P @ V.
// One block per (bh, 64-q tile); loops over 25 key tiles of 64.
// ---------------------------------------------------------------------------
__global__ __launch_bounds__(256) void out_kernel(float* __restrict__ Pext, int use_ext,
                                                  float* __restrict__ out)
{
    float* P = use_ext ? Pext : g_scores_fallback;
    const int bh = blockIdx.y;
    const int qBase = blockIdx.x * 64;
    const float* V = g_v + (size_t)bh * SEQ * HDIM;
    float* Pr = P + (size_t)bh * SEQ * SEQ;

    __shared__ float psT[64][68];  // [k][q]
    __shared__ float vs[64][68];   // [k][d]
    __shared__ float rm[64], ri[64];

    const int t = threadIdx.x;
    const int tx = t & 15, ty = t >> 4;

    if (t < 64) {
        rm[t] = g_rowmax[bh * SEQ + qBase + t];
        ri[t] = g_rowinv[bh * SEQ + qBase + t];
    }

    float acc[4][4] = {};

    for (int k0 = 0; k0 < SEQ; k0 += 64) {
        __syncthreads();   // first iter: covers rm/ri; later: guards smem reuse
        #pragma unroll
        for (int p = 0; p < 4; p++) {
            int idx = t + p * 256;
            int r   = idx >> 4;
            int cg  = (idx & 15) * 4;
            float4 v4 = *(float4*)&Pr[(size_t)(qBase + r) * SEQ + k0 + cg];
            float m = rm[r], inv = ri[r];
            float4 pv;
            pv.x = __expf(v4.x - m) * inv;
            pv.y = __expf(v4.y - m) * inv;
            pv.z = __expf(v4.z - m) * inv;
            pv.w = __expf(v4.w - m) * inv;
            *(float4*)&Pr[(size_t)(qBase + r) * SEQ + k0 + cg] = pv;  // final p_attn
            psT[cg + 0][r] = pv.x; psT[cg + 1][r] = pv.y;
            psT[cg + 2][r] = pv.z; psT[cg + 3][r] = pv.w;
            float4 vv = *(const float4*)&V[(size_t)(k0 + r) * HDIM + cg];
            *(float4*)&vs[r][cg] = vv;
        }
        __syncthreads();
        #pragma unroll
        for (int kk = 0; kk < 64; kk++) {
            float4 A = *(float4*)&psT[kk][ty * 4];
            float4 Bv = *(float4*)&vs[kk][tx * 4];
            float ar[4] = {A.x, A.y, A.z, A.w};
            float br[4] = {Bv.x, Bv.y, Bv.z, Bv.w};
            #pragma unroll
            for (int i = 0; i < 4; i++)
                #pragma unroll
                for (int j = 0; j < 4; j++)
                    acc[i][j] += ar[i] * br[j];
        }
    }

    const int b_ = bh / NHEAD, h_ = bh % NHEAD;
    #pragma unroll
    for (int i = 0; i < 4; i++) {
        int s_ = qBase + ty * 4 + i;
        float4 o;
        o.x = acc[i][0]; o.y = acc[i][1]; o.z = acc[i][2]; o.w = acc[i][3];
        *(float4*)&out[((size_t)b_ * SEQ + s_) * DMODEL + h_ * HDIM + tx * 4] = o;
    }
}

// ---------------------------------------------------------------------------
extern "C" void kernel_launch(void* const* d_in, const int* in_sizes, int n_in,
                              void* d_out, int out_size)
{
    const float* x  = (const float*)d_in[0];
    const float* wq = (const float*)d_in[1];
    const float* bq = (const float*)d_in[2];
    const float* wk = (const float*)d_in[3];
    const float* bk = (const float*)d_in[4];
    const float* wv = (const float*)d_in[5];
    const float* bv = (const float*)d_in[6];
    float* out = (float*)d_out;

    // p_attn region of d_out (if present) doubles as the score scratch buffer.
    int use_ext = ((size_t)out_size >= OUT_ELEMS + PATT_ELEMS) ? 1 : 0;
    float* Pext = out + OUT_ELEMS;

    // K1: QKV projections
    {
        dim3 grid(DMODEL / 64, (BATCH * SEQ) / 64, 3);
        qkv_kernel<<<grid, 256>>>(x, wq, bq, wk, bk, wv, bv);
    }
    // K2: raw masked scores
    {
        dim3 grid(SEQ / 64, SEQ / 64, BH);
        scores_kernel<<<grid, 256>>>(Pext, use_ext);
    }
    // K3: softmax row stats
    {
        rowstats_kernel<<<(BH * SEQ) / 8, 256>>>(Pext, use_ext);
    }
    // K4: normalize + p_attn write + out = P @ V
    {
        dim3 grid(SEQ / 64, BH);
        out_kernel<<<grid, 256>>>(Pext, use_ext, out);
    }
}